// round 7
// baseline (speedup 1.0000x reference)
#include <cuda_runtime.h>
#include <cstdint>
#include <cstddef>

#define S_LEN 512
#define BATCH 32
#define G4    1024
#define MROWS (S_LEN*BATCH)
#define NEGV  -10000.0f

// ---------------- device scratch ----------------
__device__ float g_x[MROWS*256];
__device__ float g_pre_f[MROWS*G4];
__device__ float g_pre_b[MROWS*G4];
__device__ float g_hf[MROWS*256];
__device__ float g_hb[MROWS*256];
__device__ float g_emit[MROWS*16];

// ---------------- f32x2 packed helpers ----------------
__device__ __forceinline__ void fma2(unsigned long long& d, unsigned long long a,
                                     unsigned long long b) {
    asm("fma.rn.f32x2 %0, %1, %2, %0;" : "+l"(d) : "l"(a), "l"(b));
}
__device__ __forceinline__ void add2(unsigned long long& d, unsigned long long a) {
    asm("add.rn.f32x2 %0, %0, %1;" : "+l"(d) : "l"(a));
}
__device__ __forceinline__ unsigned long long pk2(float lo, float hi) {
    unsigned long long r;
    asm("mov.b64 %0, {%1, %2};" : "=l"(r) : "f"(lo), "f"(hi));
    return r;
}
__device__ __forceinline__ void up2(unsigned long long v, float& lo, float& hi) {
    asm("mov.b64 {%0, %1}, %2;" : "=f"(lo), "=f"(hi) : "l"(v));
}

__device__ __forceinline__ float tanh_ap(float x) {
    float y;
    asm("tanh.approx.f32 %0, %1;" : "=f"(y) : "f"(x));
    return y;
}
__device__ __forceinline__ float sigf(float x) {
    return fmaf(0.5f, tanh_ap(0.5f * x), 0.5f);
}

// mbarrier ops (cluster-scope release/acquire)
__device__ __forceinline__ void mbar_init(uint32_t addr, uint32_t count) {
    asm volatile("mbarrier.init.shared.b64 [%0], %1;" :: "r"(addr), "r"(count) : "memory");
}
__device__ __forceinline__ void mbar_arrive_cluster(uint32_t raddr) {
    asm volatile("mbarrier.arrive.release.cluster.shared::cluster.b64 _, [%0];"
                 :: "r"(raddr) : "memory");
}
__device__ __forceinline__ void mbar_wait(uint32_t mbar, uint32_t par) {
    uint32_t done;
    asm volatile("{\n\t.reg .pred p;\n\t"
        "mbarrier.try_wait.parity.acquire.cluster.shared::cta.b64 p, [%1], %2;\n\t"
        "selp.b32 %0, 1, 0, p;\n\t}"
        : "=r"(done) : "r"(mbar), "r"(par) : "memory");
    while (!done) {
        asm volatile("{\n\t.reg .pred p;\n\t"
            "mbarrier.try_wait.parity.acquire.cluster.shared::cta.b64 p, [%1], %2;\n\t"
            "selp.b32 %0, 1, 0, p;\n\t}"
            : "=r"(done) : "r"(mbar), "r"(par) : "memory");
    }
}

// ---------------- kernel 1: embedding gather ----------------
__global__ void __launch_bounds__(64) k_gather(const int* __restrict__ tokens,
                                               const float* __restrict__ emb) {
    int bid = blockIdx.x;              // = s*32 + b
    int s = bid >> 5, b = bid & 31;
    int tok = tokens[b * S_LEN + s];
    const float4* src = (const float4*)(emb + (size_t)tok * 256);
    float4* dst = (float4*)(g_x + (size_t)bid * 256);
    dst[threadIdx.x] = src[threadIdx.x];
}

// ---------------- profiler-steering no-op ----------------
__global__ void k_probe() {}

// ---------------- kernel 2: input GEMM (f32x2, reg-prefetch) ----------------
__global__ void __launch_bounds__(256) k_gemm(const float* __restrict__ Wf,
                                              const float* __restrict__ bif,
                                              const float* __restrict__ bhf,
                                              const float* __restrict__ Wb,
                                              const float* __restrict__ bib,
                                              const float* __restrict__ bhb) {
    const int dir = blockIdx.z;
    const float* __restrict__ W  = dir ? Wb  : Wf;
    const float* __restrict__ b1 = dir ? bib : bif;
    const float* __restrict__ b2 = dir ? bhb : bhf;
    float* __restrict__ out = dir ? g_pre_b : g_pre_f;

    __shared__ float As[8 * 128];
    __shared__ float Bs[8 * 128];
    const int tid = threadIdx.x;
    const int m0 = blockIdx.y * 128, n0 = blockIdx.x * 128;
    const int lrow = tid >> 1, lk4 = (tid & 1) * 4;
    const float* aptr = g_x + (size_t)(m0 + lrow) * 256 + lk4;
    const float* bptr = W   + (size_t)(n0 + lrow) * 256 + lk4;
    const int ty = tid >> 4, tx = tid & 15;

    unsigned long long acc2[8][4];
#pragma unroll
    for (int i = 0; i < 8; i++)
#pragma unroll
        for (int j = 0; j < 4; j++) acc2[i][j] = 0ull;

    float4 av = *(const float4*)(aptr);
    float4 bv = *(const float4*)(bptr);

    for (int kt = 0; kt < 256; kt += 8) {
        As[(lk4 + 0) * 128 + lrow] = av.x; As[(lk4 + 1) * 128 + lrow] = av.y;
        As[(lk4 + 2) * 128 + lrow] = av.z; As[(lk4 + 3) * 128 + lrow] = av.w;
        Bs[(lk4 + 0) * 128 + lrow] = bv.x; Bs[(lk4 + 1) * 128 + lrow] = bv.y;
        Bs[(lk4 + 2) * 128 + lrow] = bv.z; Bs[(lk4 + 3) * 128 + lrow] = bv.w;
        __syncthreads();
        if (kt + 8 < 256) {
            av = *(const float4*)(aptr + kt + 8);
            bv = *(const float4*)(bptr + kt + 8);
        }
#pragma unroll
        for (int k = 0; k < 8; k++) {
            float4 a0 = *(const float4*)&As[k * 128 + ty * 8];
            float4 a1 = *(const float4*)&As[k * 128 + ty * 8 + 4];
            ulonglong2 bq0 = *(const ulonglong2*)&Bs[k * 128 + tx * 8];
            ulonglong2 bq1 = *(const ulonglong2*)&Bs[k * 128 + tx * 8 + 4];
            unsigned long long ad[8];
            ad[0] = pk2(a0.x, a0.x); ad[1] = pk2(a0.y, a0.y);
            ad[2] = pk2(a0.z, a0.z); ad[3] = pk2(a0.w, a0.w);
            ad[4] = pk2(a1.x, a1.x); ad[5] = pk2(a1.y, a1.y);
            ad[6] = pk2(a1.z, a1.z); ad[7] = pk2(a1.w, a1.w);
            unsigned long long bp[4] = {bq0.x, bq0.y, bq1.x, bq1.y};
#pragma unroll
            for (int i = 0; i < 8; i++)
#pragma unroll
                for (int jp = 0; jp < 4; jp++) fma2(acc2[i][jp], ad[i], bp[jp]);
        }
        __syncthreads();
    }
#pragma unroll
    for (int i = 0; i < 8; i++) {
        int m = m0 + ty * 8 + i;
#pragma unroll
        for (int jp = 0; jp < 2; jp++) {
            int n = n0 + tx * 8 + jp * 4;
            float v0, v1, v2, v3;
            up2(acc2[i][jp * 2 + 0], v0, v1);
            up2(acc2[i][jp * 2 + 1], v2, v3);
            float4 v;
            v.x = v0 + b1[n + 0] + b2[n + 0];
            v.y = v1 + b1[n + 1] + b2[n + 1];
            v.z = v2 + b1[n + 2] + b2[n + 2];
            v.w = v3 + b1[n + 3] + b2[n + 3];
            *(float4*)(out + (size_t)m * G4 + n) = v;
        }
    }
}

// ---------------- kernel 3: LSTM recurrence (512 thr, mbarrier cluster sync) ----------------
// smem floats: [0, 32768)       Wh transposed: w[k*128 + lr]
//              [32768, 34816)   hbuf: 2 phase x 4 batch x 256
//              [34816, 43008)   zred: 16 kg x 4 batch x 128 rows
// byte offset 172032: mbarrier (8B)
#define R4_W     0
#define R4_HBUF  32768
#define R4_ZRED  34816
#define R4_MBARB 172032
#define R4_SMEMB 172064

__global__ void __launch_bounds__(512, 1) __cluster_dims__(8, 1, 1)
k_recur(const float* __restrict__ Wh_f, const float* __restrict__ Wh_b) {
    extern __shared__ float sm[];
    const int tid = threadIdx.x;
    uint32_t r;
    asm("mov.u32 %0, %%cluster_ctarank;" : "=r"(r));
    const int c   = blockIdx.x >> 3;   // cluster id 0..15
    const int dir = c >> 3;            // 0 fwd, 1 bwd
    const int bg  = c & 7;             // batch group of 4
    const float* __restrict__ Wh   = dir ? Wh_b   : Wh_f;
    const float* __restrict__ preb = dir ? g_pre_b : g_pre_f;
    float* __restrict__ hout       = dir ? g_hb   : g_hf;

    const uint32_t smem_u32 = (uint32_t)__cvta_generic_to_shared(sm);
    const uint32_t mbar = smem_u32 + R4_MBARB;
    const uint32_t hbuf_u32 = smem_u32 + R4_HBUF * 4;

    // load Wh slice transposed: w[k*128 + lr] = Wh[(q*256 + r*32 + uu)*256 + k]
    for (int idx = tid; idx < 128 * 64; idx += 512) {      // idx over (lr, k4)
        int lr = idx >> 6, k4 = (idx & 63) << 2;
        int q = lr >> 5, uu = lr & 31;
        float4 w = *(const float4*)(Wh + (size_t)((q << 8) + ((int)r << 5) + uu) * 256 + k4);
        sm[R4_W + (k4 + 0) * 128 + lr] = w.x;
        sm[R4_W + (k4 + 1) * 128 + lr] = w.y;
        sm[R4_W + (k4 + 2) * 128 + lr] = w.z;
        sm[R4_W + (k4 + 3) * 128 + lr] = w.w;
    }
    for (int i = tid; i < 2048; i += 512) sm[R4_HBUF + i] = 0.f;
    if (tid == 0) mbar_init(mbar, 512);   // 64 producers x 8 CTAs
    __syncthreads();
    asm volatile("barrier.cluster.arrive.aligned;" ::: "memory");
    asm volatile("barrier.cluster.wait.aligned;" ::: "memory");

    const int kg = tid >> 5, ot = tid & 31;     // z-phase: 16 kgs of 16 k
    // gate-phase mapping (tid<64): 2 units per thread
    const int gb = tid >> 4, gu = tid & 15;
    const int bglob = bg * 4 + gb;
    const int ubase = ((int)r << 5) + (gu << 1);
    float c0 = 0.f, c1 = 0.f;
    int cur = 0;

    // producer precompute: remote hbuf + mbar addresses
    uint32_t rhb[8], rmb[8];
    if (tid < 64) {
#pragma unroll
        for (int rr = 0; rr < 8; ++rr) {
            asm("mapa.shared::cluster.u32 %0, %1, %2;" : "=r"(rhb[rr]) : "r"(hbuf_u32), "r"(rr));
            asm("mapa.shared::cluster.u32 %0, %1, %2;" : "=r"(rmb[rr]) : "r"(mbar), "r"(rr));
        }
    }
    const uint32_t hoffb = (uint32_t)((gb * 256 + ubase) * 4);

    float2 pre2[4] = {{0.f,0.f},{0.f,0.f},{0.f,0.f},{0.f,0.f}};
    if (tid < 64) {
        const int s0 = dir ? (S_LEN - 1) : 0;
        const float* pp = preb + (size_t)(s0 * BATCH + bglob) * G4 + ubase;
        pre2[0] = *(const float2*)(pp);       pre2[1] = *(const float2*)(pp + 256);
        pre2[2] = *(const float2*)(pp + 512); pre2[3] = *(const float2*)(pp + 768);
    }

    for (int t = 0; t < S_LEN; ++t) {
        const int s = dir ? (S_LEN - 1 - t) : t;
        if (t) mbar_wait(mbar, (t - 1) & 1);   // h(t) visible (acquire.cluster)

        // z partials: lane ot rows 4ot..4ot+3 (row-paired f32x2) x 4 batches, 16 k
        const float* hc = sm + R4_HBUF + cur * 1024;
        const float* wbase = sm + R4_W + (ot << 2);
        const int k0 = kg << 4;
        unsigned long long acc0[4], acc1[4];
#pragma unroll
        for (int b = 0; b < 4; ++b) { acc0[b] = 0ull; acc1[b] = 0ull; }

#pragma unroll
        for (int kb = 0; kb < 16; kb += 4) {
            const int k = k0 + kb;
            float4 h0 = *(const float4*)(hc + k);
            float4 h1 = *(const float4*)(hc + 256 + k);
            float4 h2 = *(const float4*)(hc + 512 + k);
            float4 h3 = *(const float4*)(hc + 768 + k);
            float ha[4][4] = {{h0.x, h1.x, h2.x, h3.x},
                              {h0.y, h1.y, h2.y, h3.y},
                              {h0.z, h1.z, h2.z, h3.z},
                              {h0.w, h1.w, h2.w, h3.w}};
#pragma unroll
            for (int j = 0; j < 4; ++j) {
                ulonglong2 w = *(const ulonglong2*)(wbase + (k + j) * 128);
#pragma unroll
                for (int b = 0; b < 4; ++b) {
                    unsigned long long hs = pk2(ha[j][b], ha[j][b]);
                    fma2(acc0[b], w.x, hs);
                    fma2(acc1[b], w.y, hs);
                }
            }
        }
        {
            float* zb = sm + R4_ZRED + kg * 512 + (ot << 2);
#pragma unroll
            for (int b = 0; b < 4; ++b) {
                ulonglong2 v; v.x = acc0[b]; v.y = acc1[b];
                *(ulonglong2*)(zb + b * 128) = v;
            }
        }
        __syncthreads();

        if (tid < 64) {
            unsigned long long z2[4];
#pragma unroll
            for (int g = 0; g < 4; ++g) z2[g] = pk2(pre2[g].x, pre2[g].y);
            const float* zb0 = sm + R4_ZRED + gb * 128 + (gu << 1);
#pragma unroll
            for (int kk = 0; kk < 16; ++kk) {
                const float* zb = zb0 + kk * 512;
                add2(z2[0], *(const unsigned long long*)(zb));
                add2(z2[1], *(const unsigned long long*)(zb + 32));
                add2(z2[2], *(const unsigned long long*)(zb + 64));
                add2(z2[3], *(const unsigned long long*)(zb + 96));
            }
            float zi0, zi1, zf0, zf1, zg0, zg1, zo0, zo1;
            up2(z2[0], zi0, zi1); up2(z2[1], zf0, zf1);
            up2(z2[2], zg0, zg1); up2(z2[3], zo0, zo1);
            c0 = sigf(zf0) * c0 + sigf(zi0) * tanh_ap(zg0);
            c1 = sigf(zf1) * c1 + sigf(zi1) * tanh_ap(zg1);
            float h0 = sigf(zo0) * tanh_ap(c0);
            float h1 = sigf(zo1) * tanh_ap(c1);
            *(float2*)(hout + (size_t)(s * BATCH + bglob) * 256 + ubase) =
                make_float2(h0, h1);

            unsigned long long pk = pk2(h0, h1);
            const uint32_t off = ((uint32_t)(cur ^ 1) << 12) + hoffb;
#pragma unroll
            for (int rr = 0; rr < 8; ++rr)
                asm volatile("st.shared::cluster.b64 [%0], %1;"
                             :: "r"(rhb[rr] + off), "l"(pk) : "memory");
#pragma unroll
            for (int rr = 0; rr < 8; ++rr) mbar_arrive_cluster(rmb[rr]);

            // prefetch next step's pre under the barrier window
            if (t + 1 < S_LEN) {
                const int s2 = dir ? (S_LEN - 2 - t) : (t + 1);
                const float* pp = preb + (size_t)(s2 * BATCH + bglob) * G4 + ubase;
                pre2[0] = *(const float2*)(pp);       pre2[1] = *(const float2*)(pp + 256);
                pre2[2] = *(const float2*)(pp + 512); pre2[3] = *(const float2*)(pp + 768);
            }
        }
        cur ^= 1;
    }
    mbar_wait(mbar, (S_LEN - 1) & 1);   // drain in-flight remote stores before exit
}

// ---------------- kernel 4: emissions (256 thr: hf/hb split + smem reduce) ----------------
__global__ void __launch_bounds__(256) k_emit(const float* __restrict__ Wt,
                                              const float* __restrict__ bt) {
    __shared__ float WtT[8192];   // [k][t], 512 x 16
    __shared__ float part[2048];  // 128 rows x 16 tags
    const int tid = threadIdx.x;
    for (int i = tid; i < 8192; i += 256) {
        int k = i >> 4, t = i & 15;
        WtT[i] = Wt[t * 512 + k];
    }
    __syncthreads();

    const int half = tid >> 7, rt = tid & 127;
    const size_t m = (size_t)blockIdx.x * 128 + rt;
    const float4* rr = (const float4*)((half ? g_hb : g_hf) + m * 256);
    const float* wb = &WtT[half * 4096];
    float acc[16];
#pragma unroll
    for (int t = 0; t < 16; ++t) acc[t] = 0.f;

#pragma unroll 4
    for (int k4 = 0; k4 < 64; ++k4) {
        float4 f = rr[k4];
        float fa[4] = {f.x, f.y, f.z, f.w};
#pragma unroll
        for (int j = 0; j < 4; ++j) {
            const float* wrow = &wb[(k4 * 4 + j) * 16];
            float4 w0 = *(const float4*)(wrow + 0);
            float4 w1 = *(const float4*)(wrow + 4);
            float4 w2 = *(const float4*)(wrow + 8);
            float4 w3 = *(const float4*)(wrow + 12);
            acc[0]  += fa[j] * w0.x; acc[1]  += fa[j] * w0.y; acc[2]  += fa[j] * w0.z; acc[3]  += fa[j] * w0.w;
            acc[4]  += fa[j] * w1.x; acc[5]  += fa[j] * w1.y; acc[6]  += fa[j] * w1.z; acc[7]  += fa[j] * w1.w;
            acc[8]  += fa[j] * w2.x; acc[9]  += fa[j] * w2.y; acc[10] += fa[j] * w2.z; acc[11] += fa[j] * w2.w;
            acc[12] += fa[j] * w3.x; acc[13] += fa[j] * w3.y; acc[14] += fa[j] * w3.z; acc[15] += fa[j] * w3.w;
        }
    }
    if (half == 0) {
#pragma unroll
        for (int t = 0; t < 16; t += 4)
            *(float4*)&part[rt * 16 + t] = make_float4(acc[t], acc[t+1], acc[t+2], acc[t+3]);
    }
    __syncthreads();
    if (half == 1) {
        float4* o = (float4*)(g_emit + m * 16);
#pragma unroll
        for (int t = 0; t < 16; t += 4) {
            float4 p = *(const float4*)&part[rt * 16 + t];
            float4 v;
            v.x = acc[t+0] + p.x + bt[t+0];
            v.y = acc[t+1] + p.y + bt[t+1];
            v.z = acc[t+2] + p.z + bt[t+2];
            v.w = acc[t+3] + p.w + bt[t+3];
            o[t >> 2] = v;
        }
    }
}

// ---------------- kernel 5: CRF forward, one block per batch ----------------
__global__ void __launch_bounds__(32) k_crf(const float* __restrict__ trans,
                                            float* __restrict__ out) {
    __shared__ float embuf[512];   // 32 steps x 16 tags
    const int b = blockIdx.x;
    const int lane = threadIdx.x;
    const int tn = lane >> 1;        // target tag
    const int tp0 = (lane & 1) * 8;  // my half of prev tags

    float tr[8];
#pragma unroll
    for (int j = 0; j < 8; ++j) tr[j] = trans[tn * 16 + tp0 + j];

    float al[8];
#pragma unroll
    for (int j = 0; j < 8; ++j) al[j] = ((tp0 + j) == 14) ? 0.f : NEGV;  // START=14

    for (int c = 0; c < 16; ++c) {   // 16 chunks of 32 steps
        for (int i = lane; i < 128; i += 32) {
            int sl = i >> 2, q = i & 3;
            ((float4*)embuf)[i] =
                *(const float4*)(g_emit + ((size_t)((c * 32 + sl) * 32 + b) * 16) + q * 4);
        }
        __syncwarp();

        for (int sl = 0; sl < 32; ++sl) {
            float m8 = -1e30f;
            float sc[8];
#pragma unroll
            for (int j = 0; j < 8; ++j) {
                sc[j] = al[j] + tr[j];
                m8 = fmaxf(m8, sc[j]);
            }
            float m = fmaxf(m8, __shfl_xor_sync(0xffffffffu, m8, 1));
            float e = 0.f;
#pragma unroll
            for (int j = 0; j < 8; ++j) e += __expf(sc[j] - m);
            e += __shfl_xor_sync(0xffffffffu, e, 1);
            float na = m + __logf(e) + embuf[sl * 16 + tn];
#pragma unroll
            for (int j = 0; j < 8; ++j)
                al[j] = __shfl_sync(0xffffffffu, na, (tp0 + j) << 1);
        }
        __syncwarp();
    }

    float m8 = -1e30f;
    float sc[8];
#pragma unroll
    for (int j = 0; j < 8; ++j) {
        sc[j] = al[j] + trans[15 * 16 + tp0 + j];
        m8 = fmaxf(m8, sc[j]);
    }
    float m = fmaxf(m8, __shfl_xor_sync(0xffffffffu, m8, 1));
    float e = 0.f;
#pragma unroll
    for (int j = 0; j < 8; ++j) e += __expf(sc[j] - m);
    e += __shfl_xor_sync(0xffffffffu, e, 1);
    if (lane == 0) out[b] = m + __logf(e);
}

// ---------------- launch ----------------
extern "C" void kernel_launch(void* const* d_in, const int* in_sizes, int n_in,
                              void* d_out, int out_size) {
    (void)in_sizes; (void)n_in; (void)out_size;
    const int*   tokens = (const int*)  d_in[0];
    const float* emb    = (const float*)d_in[1];
    const float* Wi_f   = (const float*)d_in[2];
    const float* Wh_f   = (const float*)d_in[3];
    const float* bi_f   = (const float*)d_in[4];
    const float* bh_f   = (const float*)d_in[5];
    const float* Wi_b   = (const float*)d_in[6];
    const float* Wh_b   = (const float*)d_in[7];
    const float* bi_b   = (const float*)d_in[8];
    const float* bh_b   = (const float*)d_in[9];
    const float* Wt     = (const float*)d_in[10];
    const float* bt     = (const float*)d_in[11];
    const float* trans  = (const float*)d_in[12];
    float* out = (float*)d_out;

    static int configured = 0;
    if (!configured) {
        cudaFuncSetAttribute(k_recur, cudaFuncAttributeMaxDynamicSharedMemorySize, R4_SMEMB);
        configured = 1;
    }

    k_gather<<<MROWS, 64>>>(tokens, emb);
    k_gemm<<<dim3(8, 128, 2), 256>>>(Wi_f, bi_f, bh_f, Wi_b, bi_b, bh_b);
    k_probe<<<1, 32>>>();   // keep k_recur in ncu's profiled slot
    k_recur<<<128, 512, R4_SMEMB>>>(Wh_f, Wh_b);
    k_emit<<<128, 256>>>(Wt, bt);
    k_crf<<<BATCH, 32>>>(trans, out);
}